// round 13
// baseline (speedup 1.0000x reference)
#include <cuda_runtime.h>
#include <cuda_bf16.h>

#define N_NODES   100000
#define N_EDGES   1600000
#define NUM_RELS  200
#define IN_FEAT   20
#define OUT_FEAT  20

// Fixed-capacity relation bins: mean 8000 edges/rel, sd ~89. CAP = +7.9 sigma.
#define CAP        8704
#define TOTAL_SLOTS (NUM_RELS * CAP)

// SMEM layout for edge kernel (floats):
//   W4  : transposed W as float4 rows (i=0..3), [r][b][o] -> 200*20 float4 = 16000 floats
//   WT  : W tail (i=4) scalars,                  200*20 floats            =  4000 floats
//   GW  : gate_weight                                                     =  4000 floats
//   B   : bias_term                                                       =  4000 floats
#define SM_W4_OFF  0          // float4 region (16000 floats)
#define SM_WT_OFF  16000
#define SM_GW_OFF  20000
#define SM_B_OFF   24000
#define SM_FLOATS  28000
#define SM_BYTES   (SM_FLOATS * 4)   // 112000 -> 2 CTAs/SM

// Heterogeneous prologue grid: scatter blocks + loop_msg blocks
#define SCAT_BLOCKS 782                      // 782 * 2048 >= 1.6M edges
#define LOOP_BLOCKS ((N_NODES + 255) / 256)  // 391
#define PRO_BLOCKS  (SCAT_BLOCKS + LOOP_BLOCKS)

// ---------------------------------------------------------------------------
// Static scratch (no cudaMalloc allowed)
// ---------------------------------------------------------------------------
__device__ int  g_cursor[NUM_RELS];
__device__ int2 g_edges_s[TOTAL_SLOTS];   // (src, dst) in rel-strided bins

__device__ __forceinline__ void red_add_v4(float* addr, float a, float b, float c, float d) {
    asm volatile("red.global.add.v4.f32 [%0], {%1, %2, %3, %4};"
                 :: "l"(addr), "f"(a), "f"(b), "f"(c), "f"(d)
                 : "memory");
}

// ---------------------------------------------------------------------------
// Fused prologue (round-11 exact): scatter blocks + loop-message blocks.
// ---------------------------------------------------------------------------
__global__ __launch_bounds__(256)
void prologue_kernel(const float* __restrict__ h,
                     const float* __restrict__ loop_w,
                     const int* __restrict__ src,
                     const int* __restrict__ dst,
                     const int* __restrict__ et,
                     float* __restrict__ out) {
    __shared__ int ism[2 * NUM_RELS];   // 400 ints == 400 floats

    if (blockIdx.x < SCAT_BLOCKS) {
        // ---------------- scatter path ----------------
        int* cnt  = ism;
        int* base = ism + NUM_RELS;
        const int lo = blockIdx.x * 2048;

        for (int i = threadIdx.x; i < NUM_RELS; i += blockDim.x) cnt[i] = 0;
        __syncthreads();

        int4 rv[2], sv[2], dv[2];
        int  rk[2][4];
        bool ok[2];

#pragma unroll
        for (int g = 0; g < 2; g++) {
            int b = lo + g * 1024 + threadIdx.x * 4;
            ok[g] = (b + 3) < N_EDGES;
            if (ok[g]) {
                rv[g] = *reinterpret_cast<const int4*>(et  + b);
                sv[g] = *reinterpret_cast<const int4*>(src + b);
                dv[g] = *reinterpret_cast<const int4*>(dst + b);
                rk[g][0] = atomicAdd(&cnt[rv[g].x], 1);
                rk[g][1] = atomicAdd(&cnt[rv[g].y], 1);
                rk[g][2] = atomicAdd(&cnt[rv[g].z], 1);
                rk[g][3] = atomicAdd(&cnt[rv[g].w], 1);
            }
        }
        __syncthreads();

        for (int i = threadIdx.x; i < NUM_RELS; i += blockDim.x) {
            int c = cnt[i];
            base[i] = c ? atomicAdd(&g_cursor[i], c) : 0;
        }
        __syncthreads();

#pragma unroll
        for (int g = 0; g < 2; g++) {
            if (ok[g]) {
                g_edges_s[rv[g].x * CAP + base[rv[g].x] + rk[g][0]] = make_int2(sv[g].x, dv[g].x);
                g_edges_s[rv[g].y * CAP + base[rv[g].y] + rk[g][1]] = make_int2(sv[g].y, dv[g].y);
                g_edges_s[rv[g].z * CAP + base[rv[g].z] + rk[g][2]] = make_int2(sv[g].z, dv[g].z);
                g_edges_s[rv[g].w * CAP + base[rv[g].w] + rk[g][3]] = make_int2(sv[g].w, dv[g].w);
            }
        }
    } else {
        // ---------------- loop-message path ----------------
        float* w = reinterpret_cast<float*>(ism);  // 400 floats, exactly fits
        for (int i = threadIdx.x; i < IN_FEAT * OUT_FEAT; i += blockDim.x)
            w[i] = loop_w[i];
        __syncthreads();

        int n = (blockIdx.x - SCAT_BLOCKS) * blockDim.x + threadIdx.x;
        if (n >= N_NODES) return;

        const float4* h4 = reinterpret_cast<const float4*>(h + (size_t)n * IN_FEAT);
        float x[IN_FEAT];
#pragma unroll
        for (int i = 0; i < 5; i++) {
            float4 t = h4[i];
            x[4*i+0] = t.x; x[4*i+1] = t.y; x[4*i+2] = t.z; x[4*i+3] = t.w;
        }

        float4 acc[5];
#pragma unroll
        for (int k = 0; k < 5; k++) acc[k] = make_float4(0.f, 0.f, 0.f, 0.f);

#pragma unroll
        for (int i = 0; i < IN_FEAT; i++) {
            float xi = x[i];
            const float4* wr = reinterpret_cast<const float4*>(w + i * OUT_FEAT);
#pragma unroll
            for (int k = 0; k < 5; k++) {
                float4 wv = wr[k];
                acc[k].x = fmaf(xi, wv.x, acc[k].x);
                acc[k].y = fmaf(xi, wv.y, acc[k].y);
                acc[k].z = fmaf(xi, wv.z, acc[k].z);
                acc[k].w = fmaf(xi, wv.w, acc[k].w);
            }
        }

        float4* o4 = reinterpret_cast<float4*>(out + (size_t)n * OUT_FEAT);
#pragma unroll
        for (int k = 0; k < 5; k++) o4[k] = acc[k];
    }
}

// ---------------------------------------------------------------------------
// Edge kernel: 512 thr x 2 CTAs/SM. W transposed to o-major in SMEM:
// per output element ONE LDS.128 (i=0..3) + ONE scalar LDS (i=4), consumed
// immediately (<=5 live W floats -> no spill pressure). LDS per edge: 50
// warp-instr vs 110 in the scalar form.
// ---------------------------------------------------------------------------
__global__ __launch_bounds__(512, 2)
void edge_kernel(const float* __restrict__ h,
                 const float* __restrict__ weight,      // [200, 100] = [r][b][i][o]
                 const float* __restrict__ bias_term,   // [200, 20]
                 const float* __restrict__ gate_weight, // [200, 20]
                 const float* __restrict__ gate_bias,   // [200]
                 float* __restrict__ out) {
    extern __shared__ float sm[];
    float4* w4sh = reinterpret_cast<float4*>(sm + SM_W4_OFF);
    float*  wtsh = sm + SM_WT_OFF;
    float*  gwsh = sm + SM_GW_OFF;
    float*  bsh  = sm + SM_B_OFF;

    // Stage transposed W: w4sh[r*20 + b*5 + o] = W[r][b][i=0..3][o], tail i=4
    for (int i = threadIdx.x; i < NUM_RELS * 20; i += blockDim.x) {
        int r = i / 20;
        int k = i - r * 20;
        int b = k / 5;
        int o = k - b * 5;
        const float* wsrc = weight + r * 100 + b * 25;   // [i][o], 5x5
        w4sh[i] = make_float4(wsrc[0*5 + o], wsrc[1*5 + o], wsrc[2*5 + o], wsrc[3*5 + o]);
        wtsh[i] = wsrc[4*5 + o];
    }
    for (int i = threadIdx.x; i < NUM_RELS * 20; i += blockDim.x) gwsh[i] = gate_weight[i];
    for (int i = threadIdx.x; i < NUM_RELS * 20; i += blockDim.x) bsh[i]  = bias_term[i];
    __syncthreads();

    const int stride = gridDim.x * blockDim.x;
    for (int slot = blockIdx.x * blockDim.x + threadIdx.x; slot < TOTAL_SLOTS; slot += stride) {
        int r   = slot / CAP;
        int idx = slot - r * CAP;

        // Independent loads issued together; record read always safe.
        int2 ed  = __ldg(&g_edges_s[slot]);
        int cnt  = __ldg(&g_cursor[r]);
        float gb = __ldg(&gate_bias[r]);
        if (idx >= cnt) continue;

        int s = ed.x, d = ed.y;

        // gather source features (5 outstanding LDG.128)
        const float4* h4 = reinterpret_cast<const float4*>(h + (size_t)s * IN_FEAT);
        float4 t[5];
#pragma unroll
        for (int i = 0; i < 5; i++) t[i] = __ldg(&h4[i]);
        float x[IN_FEAT];
#pragma unroll
        for (int i = 0; i < 5; i++) {
            x[4*i+0] = t[i].x; x[4*i+1] = t[i].y; x[4*i+2] = t[i].z; x[4*i+3] = t[i].w;
        }

        // gate = sigmoid(dot(x, gw[r]) + gb)
        const float4* gw4 = reinterpret_cast<const float4*>(gwsh + r * 20);
        float g = gb;
#pragma unroll
        for (int k = 0; k < 5; k++) {
            float4 wv = gw4[k];
            g = fmaf(x[4*k+0], wv.x, g);
            g = fmaf(x[4*k+1], wv.y, g);
            g = fmaf(x[4*k+2], wv.z, g);
            g = fmaf(x[4*k+3], wv.w, g);
        }
        float gate = 1.0f / (1.0f + __expf(-g));

        // block-diagonal matmul: one LDS.128 + one scalar LDS per output elem
        float m[OUT_FEAT];
        const float4* w4r = w4sh + r * 20;
        const float*  wtr = wtsh + r * 20;
#pragma unroll
        for (int b = 0; b < 4; b++) {
            float x0 = x[b*5+0], x1 = x[b*5+1], x2 = x[b*5+2], x3 = x[b*5+3], x4 = x[b*5+4];
#pragma unroll
            for (int o = 0; o < 5; o++) {
                float4 wv = w4r[b*5 + o];
                float acc =        x0 * wv.x;
                acc = fmaf(x1, wv.y, acc);
                acc = fmaf(x2, wv.z, acc);
                acc = fmaf(x3, wv.w, acc);
                acc = fmaf(x4, wtr[b*5 + o], acc);
                m[b*5 + o] = acc;
            }
        }

        // gated + biased vector scatter-add
        const float4* br4 = reinterpret_cast<const float4*>(bsh + r * 20);
        float* op = out + (size_t)d * OUT_FEAT;
#pragma unroll
        for (int k = 0; k < 5; k++) {
            float4 bv = br4[k];
            red_add_v4(op + 4*k,
                       gate * (m[4*k+0] + bv.x),
                       gate * (m[4*k+1] + bv.y),
                       gate * (m[4*k+2] + bv.z),
                       gate * (m[4*k+3] + bv.w));
        }
    }
}

// ---------------------------------------------------------------------------
// Kernel C: in-place ReLU
// ---------------------------------------------------------------------------
__global__ void relu_kernel(float* __restrict__ out, int n4) {
    int i = blockIdx.x * blockDim.x + threadIdx.x;
    if (i >= n4) return;
    float4* p = reinterpret_cast<float4*>(out);
    float4 v = p[i];
    v.x = fmaxf(v.x, 0.0f);
    v.y = fmaxf(v.y, 0.0f);
    v.z = fmaxf(v.z, 0.0f);
    v.w = fmaxf(v.w, 0.0f);
    p[i] = v;
}

// ---------------------------------------------------------------------------
// Launch
// ---------------------------------------------------------------------------
extern "C" void kernel_launch(void* const* d_in, const int* in_sizes, int n_in,
                              void* d_out, int out_size) {
    const float* h           = (const float*)d_in[0];
    const float* weight      = (const float*)d_in[1];
    const float* bias_term   = (const float*)d_in[2];
    const float* gate_weight = (const float*)d_in[3];
    const float* gate_bias   = (const float*)d_in[4];
    const float* loop_weight = (const float*)d_in[5];
    const int*   edge_src    = (const int*)d_in[6];
    const int*   edge_dst    = (const int*)d_in[7];
    const int*   etype       = (const int*)d_in[8];
    float* out = (float*)d_out;

    // Zero bin cursors (800 bytes)
    void* cur_addr = nullptr;
    cudaGetSymbolAddress(&cur_addr, g_cursor);
    cudaMemsetAsync(cur_addr, 0, NUM_RELS * sizeof(int), 0);

    // Fused prologue: scatter blocks + loop-message blocks, co-scheduled
    prologue_kernel<<<PRO_BLOCKS, 256>>>(h, loop_weight,
                                         edge_src, edge_dst, etype, out);

    // Edge kernel, 512 thr x 2 CTAs/SM
    cudaFuncSetAttribute(edge_kernel, cudaFuncAttributeMaxDynamicSharedMemorySize, SM_BYTES);
    edge_kernel<<<296, 512, SM_BYTES>>>(h, weight, bias_term, gate_weight, gate_bias, out);

    // ReLU in place
    int n4 = (N_NODES * OUT_FEAT) / 4;
    relu_kernel<<<(n4 + 255) / 256, 256>>>(out, n4);
}